// round 16
// baseline (speedup 1.0000x reference)
#include <cuda_runtime.h>
#include <cuda_bf16.h>
#include <math.h>
#include <stdint.h>

#define NN 10000
#define NE 160000
#define DI 128
#define DE 512
#define DH 256

// ---------------- scratch (device globals; no allocation allowed) ----------
__device__ __align__(16) float g_xlr[NN * 2 * DE];   // [node][xl(512) | xr(512)]
__device__ int   g_src[NE];
__device__ int   g_dst[NE];
__device__ int   g_rs[NN + 1];
__device__ int   g_cur[NN];
__device__ int   g_csrc[NE];
__device__ __align__(16) float g_m1[NN * DH];
__device__ float g_logit[NN];
__device__ __align__(16) __nv_bfloat16 g_ahi[NN * DE];
__device__ __align__(16) __nv_bfloat16 g_alo[NN * DE];
__device__ __align__(16) __nv_bfloat16 g_bhi[NN * DH];
__device__ __align__(16) __nv_bfloat16 g_blo[NN * DH];
// per-layer weight buffers (transposed, hi/lo)
__device__ __align__(16) __nv_bfloat16 g_w1hi[1024 * 128], g_w1lo[1024 * 128];
__device__ __align__(16) __nv_bfloat16 g_w2hi[1024 * 512], g_w2lo[1024 * 512];
__device__ __align__(16) __nv_bfloat16 g_w3hi[1024 * 512], g_w3lo[1024 * 512];
__device__ __align__(16) __nv_bfloat16 g_a1hi[256 * 512],  g_a1lo[256 * 512];
__device__ __align__(16) __nv_bfloat16 g_a2hi[256 * 256],  g_a2lo[256 * 256];

// ---------------- fused weight prep: all 5 matrices, one launch -------------
// per block: one 64(k) x 32(m) tile of one source matrix -> WT[m+rofs][K] hi/lo
__device__ __forceinline__ void prep_tile(const float* __restrict__ W,
                                          __nv_bfloat16* __restrict__ hiT,
                                          __nv_bfloat16* __restrict__ loT,
                                          int K, int M, int rofs, int k0, int m0) {
    __shared__ float s[64][33];
    int tid = threadIdx.x;
    #pragma unroll
    for (int i = tid; i < 64 * 32; i += 256) {
        int kk = i >> 5, mm = i & 31;
        s[kk][mm] = W[(size_t)(k0 + kk) * M + m0 + mm];
    }
    __syncthreads();
    #pragma unroll
    for (int i = tid; i < 32 * 32; i += 256) {
        int mm = i >> 5, kp = i & 31;
        float v0 = s[2 * kp][mm], v1 = s[2 * kp + 1][mm];
        __nv_bfloat162 h2 = __floats2bfloat162_rn(v0, v1);
        float l0 = v0 - __bfloat162float(__low2bfloat16(h2));
        float l1 = v1 - __bfloat162float(__high2bfloat16(h2));
        __nv_bfloat162 l2 = __floats2bfloat162_rn(l0, l1);
        size_t ro = (size_t)(m0 + mm + rofs) * K + k0 + 2 * kp;
        *(uint32_t*)(hiT + ro) = *(uint32_t*)&h2;
        *(uint32_t*)(loT + ro) = *(uint32_t*)&l2;
    }
}

// segment boundaries (blocks of 64k x 32m):
// [0,32) L1Wl  [32,64) L1Wr      (K=128, M=512)
// [64,192) L2Wl [192,320) L2Wr   (K=512, M=512)
// [320,448) L3Wl [448,576) L3Wr
// [576,640) A1 (K=512, M=256)    [640,672) A2 (K=256, M=256)
__global__ __launch_bounds__(256) void k_prep_all(
    const float* Wl1, const float* Wr1, const float* Wl2, const float* Wr2,
    const float* Wl3, const float* Wr3, const float* A1, const float* A2) {
    int b = blockIdx.x;
    const float* W; __nv_bfloat16 *hi, *lo; int K, M, rofs, local, nkb;
    if (b < 64)        { W = (b < 32) ? Wl1 : Wr1; hi = g_w1hi; lo = g_w1lo; K = 128; M = 512; rofs = (b < 32) ? 0 : 512; local = b & 31; nkb = 2; }
    else if (b < 320)  { W = (b < 192) ? Wl2 : Wr2; hi = g_w2hi; lo = g_w2lo; K = 512; M = 512; rofs = (b < 192) ? 0 : 512; local = (b - 64) & 127; nkb = 8; }
    else if (b < 576)  { W = (b < 448) ? Wl3 : Wr3; hi = g_w3hi; lo = g_w3lo; K = 512; M = 512; rofs = (b < 448) ? 0 : 512; local = (b - 320) & 127; nkb = 8; }
    else if (b < 640)  { W = A1; hi = g_a1hi; lo = g_a1lo; K = 512; M = 256; rofs = 0; local = b - 576; nkb = 8; }
    else               { W = A2; hi = g_a2hi; lo = g_a2lo; K = 256; M = 256; rofs = 0; local = b - 640; nkb = 4; }
    int k0 = (local % nkb) * 64;
    int m0 = (local / nkb) * 32;
    prep_tile(W, hi, lo, K, M, rofs, k0, m0);
}

// ---------------- edge decode (detect inline) + layer-1 split ---------------
__global__ void k_edges_split(const int* __restrict__ w, const float* __restrict__ x,
                              __nv_bfloat16* __restrict__ hi, __nv_bfloat16* __restrict__ lo,
                              int nsplit) {
    __shared__ int s;
    if (threadIdx.x == 0) s = 0;
    __syncthreads();
    int acc = 0;
    for (int i = threadIdx.x; i < 2048; i += 256) acc |= w[2 * i + 1];
    atomicOr(&s, acc);
    __syncthreads();
    int is64 = (s == 0);

    int i = blockIdx.x * 256 + threadIdx.x;
    if (i < NE) {
        int sv, d;
        if (is64) { sv = w[2 * i]; d = w[2 * (NE + i)]; }
        else      { sv = w[i];     d = w[NE + i]; }
        if ((unsigned)sv >= NN) sv = 0;
        if ((unsigned)d >= NN) d = 0;
        g_src[i] = sv;
        g_dst[i] = d;
    } else {
        int j = i - NE;
        if (j < nsplit) {
            float v = x[j];
            __nv_bfloat16 h = __float2bfloat16_rn(v);
            hi[j] = h;
            lo[j] = __float2bfloat16_rn(v - __bfloat162float(h));
        }
    }
}

// ---------------- single-block: smem histogram + scan (+ zero logit) --------
__global__ __launch_bounds__(1024) void k_scan() {
    __shared__ int sdeg[NN];     // 40 KB
    __shared__ int wsum[32];
    __shared__ int sbase;
    int t = threadIdx.x;
    int lane = t & 31, w = t >> 5;
    for (int i = t; i < NN; i += 1024) { sdeg[i] = 0; g_logit[i] = 0.f; }
    if (t == 0) sbase = 0;
    __syncthreads();
    for (int e = t; e < NE; e += 1024) atomicAdd(&sdeg[g_dst[e]], 1);
    __syncthreads();
    for (int c = 0; c < NN; c += 1024) {
        int idx = c + t;
        int v = (idx < NN) ? sdeg[idx] : 0;
        int inc = v;
        #pragma unroll
        for (int o = 1; o < 32; o <<= 1) {
            int u = __shfl_up_sync(0xffffffffu, inc, o);
            if (lane >= o) inc += u;
        }
        if (lane == 31) wsum[w] = inc;
        __syncthreads();
        if (w == 0) {
            int vv = wsum[lane];
            #pragma unroll
            for (int o = 1; o < 32; o <<= 1) {
                int u = __shfl_up_sync(0xffffffffu, vv, o);
                if (lane >= o) vv += u;
            }
            wsum[lane] = vv;
        }
        __syncthreads();
        int base = sbase + ((w > 0) ? wsum[w - 1] : 0) + inc - v;
        if (idx < NN) { g_rs[idx] = base; g_cur[idx] = base; }
        __syncthreads();
        if (t == 0) sbase += wsum[31];
        __syncthreads();
    }
    if (t == 0) g_rs[NN] = sbase;
}

__global__ void k_scatter() {
    int i = blockIdx.x * blockDim.x + threadIdx.x;
    if (i >= NE) return;
    int pos = atomicAdd(&g_cur[g_dst[i]], 1);
    g_csrc[pos] = g_src[i];
}

// ---------------- persistent cp.async + ldmatrix bf16 GEMM (3-pass hi/lo) ---
#define TPAD 40
#define TILE_E (128 * TPAD)
#define STAGE_E (4 * TILE_E)
#define SMEM_GEMM (2 * STAGE_E * 2)
#define GEMM_CTAS 296

__device__ __forceinline__ void cpa16(uint32_t dst, const void* src, int sz) {
    asm volatile("cp.async.cg.shared.global [%0], [%1], 16, %2;"
                 :: "r"(dst), "l"(src), "r"(sz) : "memory");
}
__device__ __forceinline__ void cpa_commit() {
    asm volatile("cp.async.commit_group;" ::: "memory");
}
template<int N> __device__ __forceinline__ void cpa_wait() {
    asm volatile("cp.async.wait_group %0;" :: "n"(N) : "memory");
}
__device__ __forceinline__ void ldsm4(uint32_t* r, uint32_t addr) {
    asm volatile("ldmatrix.sync.aligned.m8n8.x4.shared.b16 {%0,%1,%2,%3}, [%4];"
                 : "=r"(r[0]), "=r"(r[1]), "=r"(r[2]), "=r"(r[3]) : "r"(addr));
}

// mode bits: 1 = bias + leaky(0.1); 2 = write bf16 hi/lo to Hi/Lo;
//            4 = partial dot with A3v -> atomicAdd g_logit[row]; 8 = skip C write
__global__ __launch_bounds__(256, 2) void k_gemm_mma(
    const __nv_bfloat16* __restrict__ Ahi, const __nv_bfloat16* __restrict__ Alo,
    const __nv_bfloat16* __restrict__ BhiT, const __nv_bfloat16* __restrict__ BloT,
    float* __restrict__ C, int Nrows, int K, int M,
    const float* __restrict__ bias, int mode,
    __nv_bfloat16* __restrict__ Hi, __nv_bfloat16* __restrict__ Lo,
    const float* __restrict__ A3v)
{
    extern __shared__ __nv_bfloat16 smem[];
    uint32_t sb = (uint32_t)__cvta_generic_to_shared(smem);

    int tid = threadIdx.x;
    int wid = tid >> 5, lane = tid & 31;
    int wm = wid & 1, wn = wid >> 1;
    int mBase = wm * 64, nBase = wn * 32;
    int g = lane >> 2, cw = lane & 3;
    int mat = lane >> 3, r8 = lane & 7;
    int rsel = (mat & 1) * 8 + r8;
    int csel = (mat >> 1) * 8;

    int nk = K / 32;               // even for all K used
    int c0 = tid * 2;
    int ntx = M / 128;
    int ntiles = ntx * ((Nrows + 127) / 128);

    for (int tile = blockIdx.x; tile < ntiles; tile += gridDim.x) {
        int row0 = (tile / ntx) * 128;
        int col0 = (tile % ntx) * 128;

        float acc[4][4][4];
        #pragma unroll
        for (int a = 0; a < 4; a++)
            #pragma unroll
            for (int b = 0; b < 4; b++)
                #pragma unroll
                for (int c = 0; c < 4; c++) acc[a][b][c] = 0.f;

        auto prefetch = [&](int ck, int stage) {
            int kofs = ck * 32;
            uint32_t se = (uint32_t)stage * STAGE_E;
            #pragma unroll
            for (int i = 0; i < 2; i++) {
                int c = c0 + i;
                int r = c >> 2, seg = c & 3;
                uint32_t dA = sb + 2 * (se + r * TPAD + seg * 8);
                int gr = row0 + r;
                int szA = (gr < Nrows) ? 16 : 0;
                const __nv_bfloat16* pa = Ahi + (size_t)gr * K + kofs + seg * 8;
                const __nv_bfloat16* pl = Alo + (size_t)gr * K + kofs + seg * 8;
                if (szA == 0) { pa = Ahi; pl = Alo; }
                cpa16(dA, pa, szA);
                cpa16(dA + 2 * TILE_E, pl, szA);
                const __nv_bfloat16* pb = BhiT + (size_t)(col0 + r) * K + kofs + seg * 8;
                const __nv_bfloat16* pq = BloT + (size_t)(col0 + r) * K + kofs + seg * 8;
                cpa16(dA + 2 * (2 * TILE_E), pb, 16);
                cpa16(dA + 2 * (3 * TILE_E), pq, 16);
            }
            cpa_commit();
        };

        prefetch(0, 0);

        for (int ck = 0; ck < nk; ck++) {
            int stage = ck & 1;
            cpa_wait<0>();
            __syncthreads();
            if (ck + 1 < nk) prefetch(ck + 1, stage ^ 1);

            uint32_t se = (uint32_t)stage * STAGE_E;
            #pragma unroll
            for (int pass = 0; pass < 3; pass++) {
                uint32_t aoff = se + ((pass == 1) ? TILE_E : 0u);
                uint32_t boff = se + ((pass == 2) ? 3u * TILE_E : 2u * TILE_E);
                #pragma unroll
                for (int ks = 0; ks < 2; ks++) {
                    int kw = ks * 16 + csel;
                    uint32_t af[4][4];
                    #pragma unroll
                    for (int mi = 0; mi < 4; mi++)
                        ldsm4(af[mi], sb + 2 * (aoff + (uint32_t)(mBase + mi * 16 + rsel) * TPAD + kw));
                    uint32_t bfr[2][4];
                    #pragma unroll
                    for (int p = 0; p < 2; p++)
                        ldsm4(bfr[p], sb + 2 * (boff + (uint32_t)(nBase + p * 16 + rsel) * TPAD + kw));
                    #pragma unroll
                    for (int mi = 0; mi < 4; mi++)
                        #pragma unroll
                        for (int ni = 0; ni < 4; ni++) {
                            float* d = acc[mi][ni];
                            uint32_t b0 = bfr[ni >> 1][ni & 1];
                            uint32_t b1 = bfr[ni >> 1][2 + (ni & 1)];
                            asm volatile(
                                "mma.sync.aligned.m16n8k16.row.col.f32.bf16.bf16.f32 "
                                "{%0,%1,%2,%3}, {%4,%5,%6,%7}, {%8,%9}, {%0,%1,%2,%3};"
                                : "+f"(d[0]), "+f"(d[1]), "+f"(d[2]), "+f"(d[3])
                                : "r"(af[mi][0]), "r"(af[mi][1]), "r"(af[mi][2]), "r"(af[mi][3]),
                                  "r"(b0), "r"(b1));
                        }
                }
            }
        }

        #pragma unroll
        for (int mi = 0; mi < 4; mi++) {
            int r0 = row0 + mBase + mi * 16 + g;
            float dot0 = 0.f, dot1 = 0.f;
            #pragma unroll
            for (int ni = 0; ni < 4; ni++) {
                int cc = col0 + nBase + ni * 8 + cw * 2;
                float v0 = acc[mi][ni][0], v1 = acc[mi][ni][1];
                float v2 = acc[mi][ni][2], v3 = acc[mi][ni][3];
                if (mode & 1) {
                    float b0 = bias[cc], b1 = bias[cc + 1];
                    v0 += b0; v0 = (v0 > 0.f) ? v0 : 0.1f * v0;
                    v1 += b1; v1 = (v1 > 0.f) ? v1 : 0.1f * v1;
                    v2 += b0; v2 = (v2 > 0.f) ? v2 : 0.1f * v2;
                    v3 += b1; v3 = (v3 > 0.f) ? v3 : 0.1f * v3;
                }
                if (mode & 4) {
                    float w0 = A3v[cc], w1 = A3v[cc + 1];
                    dot0 += v0 * w0 + v1 * w1;
                    dot1 += v2 * w0 + v3 * w1;
                }
                if (r0 < Nrows) {
                    if (!(mode & 8))
                        *(float2*)(C + (size_t)r0 * M + cc) = make_float2(v0, v1);
                    if (mode & 2) {
                        __nv_bfloat162 h2 = __floats2bfloat162_rn(v0, v1);
                        float l0 = v0 - __bfloat162float(__low2bfloat16(h2));
                        float l1 = v1 - __bfloat162float(__high2bfloat16(h2));
                        __nv_bfloat162 l2 = __floats2bfloat162_rn(l0, l1);
                        *(uint32_t*)(Hi + (size_t)r0 * M + cc) = *(uint32_t*)&h2;
                        *(uint32_t*)(Lo + (size_t)r0 * M + cc) = *(uint32_t*)&l2;
                    }
                }
                if (r0 + 8 < Nrows) {
                    if (!(mode & 8))
                        *(float2*)(C + (size_t)(r0 + 8) * M + cc) = make_float2(v2, v3);
                    if (mode & 2) {
                        __nv_bfloat162 h2 = __floats2bfloat162_rn(v2, v3);
                        float l0 = v2 - __bfloat162float(__low2bfloat16(h2));
                        float l1 = v3 - __bfloat162float(__high2bfloat16(h2));
                        __nv_bfloat162 l2 = __floats2bfloat162_rn(l0, l1);
                        *(uint32_t*)(Hi + (size_t)(r0 + 8) * M + cc) = *(uint32_t*)&h2;
                        *(uint32_t*)(Lo + (size_t)(r0 + 8) * M + cc) = *(uint32_t*)&l2;
                    }
                }
            }
            if (mode & 4) {
                #pragma unroll
                for (int o = 1; o < 4; o <<= 1) {
                    dot0 += __shfl_xor_sync(0xffffffffu, dot0, o);
                    dot1 += __shfl_xor_sync(0xffffffffu, dot1, o);
                }
                if (cw == 0) {
                    if (r0 < Nrows)     atomicAdd(&g_logit[r0], dot0);
                    if (r0 + 8 < Nrows) atomicAdd(&g_logit[r0 + 8], dot1);
                }
            }
        }
    }
}

// ---------------- fused GATv2 edge kernel: one-pass online softmax ----------
__global__ __launch_bounds__(256) void k_gat_edge(const float* __restrict__ att,
                                                  const float* __restrict__ bias) {
    int gw = (blockIdx.x * 256 + threadIdx.x) >> 5;
    int lane = threadIdx.x & 31;
    if (gw >= NN) return;
    int d = gw;
    int rs = g_rs[d], re = g_rs[d + 1];

    float4 xr4[4], at4[4];
    const float4* pxr = (const float4*)(g_xlr + (size_t)d * 1024 + 512);
    const float4* pat = (const float4*)att;
    #pragma unroll
    for (int j = 0; j < 4; j++) {
        xr4[j] = pxr[j * 32 + lane];
        at4[j] = pat[j * 32 + lane];
    }

    float m = -3.0e38f;
    float den = 0.f;
    float accf[16];
    #pragma unroll
    for (int j = 0; j < 16; j++) accf[j] = 0.f;

    for (int e = rs; e < re; e++) {
        int s = g_csrc[e];
        const float4* pxl = (const float4*)(g_xlr + (size_t)s * 1024);
        float4 a[4];
        float lg = 0.f;
        #pragma unroll
        for (int j = 0; j < 4; j++) {
            a[j] = pxl[j * 32 + lane];
            float v;
            v = a[j].x + xr4[j].x; v = v > 0.f ? v : 0.2f * v; lg += v * at4[j].x;
            v = a[j].y + xr4[j].y; v = v > 0.f ? v : 0.2f * v; lg += v * at4[j].y;
            v = a[j].z + xr4[j].z; v = v > 0.f ? v : 0.2f * v; lg += v * at4[j].z;
            v = a[j].w + xr4[j].w; v = v > 0.f ? v : 0.2f * v; lg += v * at4[j].w;
        }
        #pragma unroll
        for (int o = 16; o; o >>= 1) lg += __shfl_xor_sync(0xffffffffu, lg, o);

        if (lg > m) {
            float sc = expf(m - lg);   // first edge: exp(-inf)=0 zeroes state
            den *= sc;
            #pragma unroll
            for (int j = 0; j < 16; j++) accf[j] *= sc;
            m = lg;
        }
        float w = expf(lg - m);
        den += w;
        #pragma unroll
        for (int j = 0; j < 4; j++) {
            accf[4 * j + 0] += w * a[j].x;
            accf[4 * j + 1] += w * a[j].y;
            accf[4 * j + 2] += w * a[j].z;
            accf[4 * j + 3] += w * a[j].w;
        }
    }

    float inv = 1.0f / (den + 1e-16f);
    const float4* pb = (const float4*)bias;
    __nv_bfloat16* ph = g_ahi + (size_t)d * DE;
    __nv_bfloat16* pl = g_alo + (size_t)d * DE;
    #pragma unroll
    for (int j = 0; j < 4; j++) {
        float4 b = pb[j * 32 + lane];
        float t0 = tanhf(accf[4 * j + 0] * inv + b.x);
        float t1 = tanhf(accf[4 * j + 1] * inv + b.y);
        float t2 = tanhf(accf[4 * j + 2] * inv + b.z);
        float t3 = tanhf(accf[4 * j + 3] * inv + b.w);
        __nv_bfloat162 h01 = __floats2bfloat162_rn(t0, t1);
        __nv_bfloat162 h23 = __floats2bfloat162_rn(t2, t3);
        float l0 = t0 - __bfloat162float(__low2bfloat16(h01));
        float l1 = t1 - __bfloat162float(__high2bfloat16(h01));
        float l2 = t2 - __bfloat162float(__low2bfloat16(h23));
        float l3 = t3 - __bfloat162float(__high2bfloat16(h23));
        __nv_bfloat162 q01 = __floats2bfloat162_rn(l0, l1);
        __nv_bfloat162 q23 = __floats2bfloat162_rn(l2, l3);
        uint2 uh, ul;
        uh.x = *(uint32_t*)&h01; uh.y = *(uint32_t*)&h23;
        ul.x = *(uint32_t*)&q01; ul.y = *(uint32_t*)&q23;
        ((uint2*)ph)[j * 32 + lane] = uh;
        ((uint2*)pl)[j * 32 + lane] = ul;
    }
}

// ---------------- softmax over nodes (register-cached, 1 global pass) -------
__global__ void k_softmax(float* __restrict__ out) {
    __shared__ float sh[1024];
    int t = threadIdx.x;
    float v[10];
    float m = -3.0e38f;
    #pragma unroll
    for (int j = 0; j < 10; j++) {
        int idx = t + j * 1024;
        v[j] = (idx < NN) ? g_logit[idx] : -3.0e38f;
        m = fmaxf(m, v[j]);
    }
    sh[t] = m; __syncthreads();
    for (int s = 512; s; s >>= 1) { if (t < s) sh[t] = fmaxf(sh[t], sh[t + s]); __syncthreads(); }
    float gm = sh[0]; __syncthreads();
    float sum = 0.f;
    #pragma unroll
    for (int j = 0; j < 10; j++) {
        int idx = t + j * 1024;
        if (idx < NN) { v[j] = expf(v[j] - gm); sum += v[j]; }
    }
    sh[t] = sum; __syncthreads();
    for (int s = 512; s; s >>= 1) { if (t < s) sh[t] += sh[t + s]; __syncthreads(); }
    float gs = sh[0];
    float inv = 1.0f / gs;
    #pragma unroll
    for (int j = 0; j < 10; j++) {
        int idx = t + j * 1024;
        if (idx < NN) out[idx] = v[j] * inv;
    }
}

// ---------------- host side -------------------------------------------------
static __nv_bfloat16 *s_ahi, *s_alo, *s_bhi, *s_blo;
static __nv_bfloat16 *s_w1hi, *s_w1lo, *s_w2hi, *s_w2lo, *s_w3hi, *s_w3lo;
static __nv_bfloat16 *s_a1hi, *s_a1lo, *s_a2hi, *s_a2lo;

static void run_gemm(const __nv_bfloat16* Ahi, const __nv_bfloat16* Alo,
                     const __nv_bfloat16* Bhi, const __nv_bfloat16* Blo,
                     int K, int M, float* Cout, const float* bias, int mode,
                     __nv_bfloat16* Hi, __nv_bfloat16* Lo, const float* A3v) {
    int ntiles = (M / 128) * ((NN + 127) / 128);
    int grid = (ntiles < GEMM_CTAS) ? ntiles : GEMM_CTAS;
    k_gemm_mma<<<grid, 256, SMEM_GEMM>>>(Ahi, Alo, Bhi, Blo, Cout, NN, K, M,
                                         bias, mode, Hi, Lo, A3v);
}

extern "C" void kernel_launch(void* const* d_in, const int* in_sizes, int n_in,
                              void* d_out, int out_size) {
    const float* x   = (const float*)d_in[0];
    const int*   ei  = (const int*)d_in[1];
    const float* Wl1 = (const float*)d_in[2];
    const float* Wr1 = (const float*)d_in[3];
    const float* at1 = (const float*)d_in[4];
    const float* b1  = (const float*)d_in[5];
    const float* Wl2 = (const float*)d_in[6];
    const float* Wr2 = (const float*)d_in[7];
    const float* at2 = (const float*)d_in[8];
    const float* b2  = (const float*)d_in[9];
    const float* Wl3 = (const float*)d_in[10];
    const float* Wr3 = (const float*)d_in[11];
    const float* at3 = (const float*)d_in[12];
    const float* b3  = (const float*)d_in[13];
    const float* A1  = (const float*)d_in[14];
    const float* c1  = (const float*)d_in[15];
    const float* A2  = (const float*)d_in[16];
    const float* c2  = (const float*)d_in[17];
    const float* A3  = (const float*)d_in[18];
    // c3 cancels exactly in the node softmax (constant shift) — unused.
    float* out = (float*)d_out;

    cudaFuncSetAttribute(k_gemm_mma, cudaFuncAttributeMaxDynamicSharedMemorySize, SMEM_GEMM);

    float *xlr, *m1;
    cudaGetSymbolAddress((void**)&xlr, g_xlr);
    cudaGetSymbolAddress((void**)&m1,  g_m1);
    cudaGetSymbolAddress((void**)&s_ahi, g_ahi);
    cudaGetSymbolAddress((void**)&s_alo, g_alo);
    cudaGetSymbolAddress((void**)&s_bhi, g_bhi);
    cudaGetSymbolAddress((void**)&s_blo, g_blo);
    cudaGetSymbolAddress((void**)&s_w1hi, g_w1hi);
    cudaGetSymbolAddress((void**)&s_w1lo, g_w1lo);
    cudaGetSymbolAddress((void**)&s_w2hi, g_w2hi);
    cudaGetSymbolAddress((void**)&s_w2lo, g_w2lo);
    cudaGetSymbolAddress((void**)&s_w3hi, g_w3hi);
    cudaGetSymbolAddress((void**)&s_w3lo, g_w3lo);
    cudaGetSymbolAddress((void**)&s_a1hi, g_a1hi);
    cudaGetSymbolAddress((void**)&s_a1lo, g_a1lo);
    cudaGetSymbolAddress((void**)&s_a2hi, g_a2hi);
    cudaGetSymbolAddress((void**)&s_a2lo, g_a2lo);

    // all weight prep in one launch (off the critical chain)
    k_prep_all<<<672, 256>>>(Wl1, Wr1, Wl2, Wr2, Wl3, Wr3, A1, A2);

    // edge decode + layer-1 split; then single-block hist+scan; then scatter
    k_edges_split<<<(NE + NN * DI + 255) / 256, 256>>>(ei, x, s_ahi, s_alo, NN * DI);
    k_scan<<<1, 1024>>>();
    k_scatter<<<(NE + 255) / 256, 256>>>();

    // layer 1
    run_gemm(s_ahi, s_alo, s_w1hi, s_w1lo, DI, 2 * DE, xlr, nullptr, 0, nullptr, nullptr, nullptr);
    k_gat_edge<<<(NN * 32 + 255) / 256, 256>>>(at1, b1);
    // layer 2
    run_gemm(s_ahi, s_alo, s_w2hi, s_w2lo, DE, 2 * DE, xlr, nullptr, 0, nullptr, nullptr, nullptr);
    k_gat_edge<<<(NN * 32 + 255) / 256, 256>>>(at2, b2);
    // layer 3
    run_gemm(s_ahi, s_alo, s_w3hi, s_w3lo, DE, 2 * DE, xlr, nullptr, 0, nullptr, nullptr, nullptr);
    k_gat_edge<<<(NN * 32 + 255) / 256, 256>>>(at3, b3);

    // MLP: gemm1 fuses bias+leaky+split; gemm2 fuses bias+leaky+logit dot (no C write)
    run_gemm(s_ahi, s_alo, s_a1hi, s_a1lo, DE, DH, m1, c1, 3, s_bhi, s_blo, nullptr);
    run_gemm(s_bhi, s_blo, s_a2hi, s_a2lo, DH, DH, m1, c2, 1 | 4 | 8, nullptr, nullptr, A3);
    k_softmax<<<1, 1024>>>(out);
}